// round 8
// baseline (speedup 1.0000x reference)
#include <cuda_runtime.h>
#include <cuda_bf16.h>
#include <cstdint>
#include <math.h>

#define BATCH   2
#define SEQ     2048
#define HIDDEN  1024
#define NHEADS  16
#define HEADD   64
#define MROWS   (BATCH*SEQ)      // 4096
#define QKVDIM  (3*HIDDEN)       // 3072
#define KSPLIT  3072             // K' for dense GEMMs
#define KQK     192              // K' for scores (3*64)
#define ATT_SCALE 0.125f
#define LNEPS   1e-5f

// ---------------- scratch (static device memory) ---------------------------
__device__ __nv_bfloat16 g_a2[(size_t)MROWS * KSPLIT];
__device__ __nv_bfloat16 g_wqkv2[(size_t)QKVDIM * KSPLIT];
__device__ __nv_bfloat16 g_wout2[(size_t)HIDDEN * KSPLIT];
__device__ __nv_bfloat16 g_attn2[(size_t)MROWS * KSPLIT];
__device__ float g_qkv[(size_t)MROWS * QKVDIM];
__device__ __nv_bfloat16 g_q2[(size_t)BATCH * NHEADS * SEQ * KQK];
__device__ __nv_bfloat16 g_k2[(size_t)BATCH * NHEADS * SEQ * KQK];
__device__ float g_probs_fb[(size_t)BATCH * NHEADS * SEQ * SEQ];

__device__ __forceinline__ uint32_t smem_u32(const void* p) {
    uint32_t a;
    asm("{ .reg .u64 t; cvta.to.shared.u64 t, %1; cvt.u32.u64 %0, t; }" : "=r"(a) : "l"(p));
    return a;
}

// ---------------- bf16 split helpers ----------------------------------------
__device__ __forceinline__ unsigned short bfb(float v) {
    __nv_bfloat16 h = __float2bfloat16(v);
    return *(unsigned short*)&h;
}
__device__ __forceinline__ float bf2f(unsigned short u) {
    __nv_bfloat16 h = *(__nv_bfloat16*)&u;
    return __bfloat162float(h);
}
__device__ __forceinline__ uint32_t pack_hi2(float a, float b) {
    return (uint32_t)bfb(a) | ((uint32_t)bfb(b) << 16);
}
__device__ __forceinline__ uint32_t pack_lo2(float a, float b) {
    unsigned short ha = bfb(a), hb = bfb(b);
    return (uint32_t)bfb(a - bf2f(ha)) | ((uint32_t)bfb(b - bf2f(hb)) << 16);
}
__device__ __forceinline__ void store_split4(__nv_bfloat16* rowbase, int k,
                                             float v0, float v1, float v2, float v3) {
    uint2 hw = { pack_hi2(v0, v1), pack_hi2(v2, v3) };
    uint2 lw = { pack_lo2(v0, v1), pack_lo2(v2, v3) };
    *(uint2*)(rowbase + k)        = hw;
    *(uint2*)(rowbase + 1024 + k) = hw;
    *(uint2*)(rowbase + 2048 + k) = lw;
}
__device__ __forceinline__ void store_split2(__nv_bfloat16* rowbase, int k, float a, float b) {
    uint32_t hw = pack_hi2(a, b), lw = pack_lo2(a, b);
    *(uint32_t*)(rowbase + k)        = hw;
    *(uint32_t*)(rowbase + 1024 + k) = hw;
    *(uint32_t*)(rowbase + 2048 + k) = lw;
}

// ---------------- LayerNorm -> split bf16 -----------------------------------
__global__ void ln_kernel(const float* __restrict__ hs,
                          const float* __restrict__ gamma,
                          const float* __restrict__ beta) {
    int row = blockIdx.x;
    int t = threadIdx.x;
    const float4* x4 = (const float4*)(hs + (size_t)row * HIDDEN);
    float4 v = x4[t];
    float s  = v.x + v.y + v.z + v.w;
    float sq = v.x*v.x + v.y*v.y + v.z*v.z + v.w*v.w;
    #pragma unroll
    for (int o = 16; o > 0; o >>= 1) {
        s  += __shfl_xor_sync(0xffffffffu, s,  o);
        sq += __shfl_xor_sync(0xffffffffu, sq, o);
    }
    __shared__ float ss[8], ssq[8];
    if ((t & 31) == 0) { ss[t >> 5] = s; ssq[t >> 5] = sq; }
    __syncthreads();
    float tot = 0.f, totq = 0.f;
    #pragma unroll
    for (int i = 0; i < 8; i++) { tot += ss[i]; totq += ssq[i]; }
    float mean = tot * (1.0f / HIDDEN);
    float var  = totq * (1.0f / HIDDEN) - mean * mean;
    float inv  = rsqrtf(var + LNEPS);

    float4 g = ((const float4*)gamma)[t];
    float4 b = ((const float4*)beta)[t];
    float o0 = (v.x - mean) * inv * g.x + b.x;
    float o1 = (v.y - mean) * inv * g.y + b.y;
    float o2 = (v.z - mean) * inv * g.z + b.z;
    float o3 = (v.w - mean) * inv * g.w + b.w;
    store_split4(g_a2 + (size_t)row * KSPLIT, t * 4, o0, o1, o2, o3);
}

// ---------------- weight conversion -----------------------------------------
__global__ void conv_w(const float* __restrict__ W, __nv_bfloat16* __restrict__ W2, int total) {
    int gid = blockIdx.x * blockDim.x + threadIdx.x;
    int i4 = gid * 4;
    if (i4 >= total) return;
    int n = i4 >> 10, k = i4 & 1023;
    float4 w = *(const float4*)(W + i4);
    uint2 hw = { pack_hi2(w.x, w.y), pack_hi2(w.z, w.w) };
    uint2 lw = { pack_lo2(w.x, w.y), pack_lo2(w.z, w.w) };
    __nv_bfloat16* rb = W2 + (size_t)n * KSPLIT;
    *(uint2*)(rb + k)        = hw;
    *(uint2*)(rb + 1024 + k) = lw;
    *(uint2*)(rb + 2048 + k) = hw;
}

// ---------------- mma plumbing ----------------------------------------------
#define SROWB   80         // bytes per smem row (32 bf16 + 8 pad)
#define KCHUNK  32
#define STAGES  4
#define OPB     (128 * SROWB)     // 10240
#define STAGEB2 (2 * OPB)         // 20480
#define DYNSM   (STAGES * STAGEB2) // 81920

__device__ __forceinline__ void ldmat4(uint32_t& r0, uint32_t& r1,
                                       uint32_t& r2, uint32_t& r3, uint32_t addr) {
    asm volatile("ldmatrix.sync.aligned.m8n8.x4.shared.b16 {%0,%1,%2,%3}, [%4];"
                 : "=r"(r0), "=r"(r1), "=r"(r2), "=r"(r3) : "r"(addr));
}
__device__ __forceinline__ void ldmat4t(uint32_t& r0, uint32_t& r1,
                                        uint32_t& r2, uint32_t& r3, uint32_t addr) {
    asm volatile("ldmatrix.sync.aligned.m8n8.x4.trans.shared.b16 {%0,%1,%2,%3}, [%4];"
                 : "=r"(r0), "=r"(r1), "=r"(r2), "=r"(r3) : "r"(addr));
}
__device__ __forceinline__ void mma16816(float* c, const uint32_t* a, uint32_t b0, uint32_t b1) {
    asm volatile("mma.sync.aligned.m16n8k16.row.col.f32.bf16.bf16.f32 "
                 "{%0,%1,%2,%3}, {%4,%5,%6,%7}, {%8,%9}, {%0,%1,%2,%3};"
                 : "+f"(c[0]), "+f"(c[1]), "+f"(c[2]), "+f"(c[3])
                 : "r"(a[0]), "r"(a[1]), "r"(a[2]), "r"(a[3]), "r"(b0), "r"(b1));
}
__device__ __forceinline__ void cpasync16(uint32_t s, const void* g) {
    asm volatile("cp.async.cg.shared.global [%0], [%1], 16;" :: "r"(s), "l"(g));
}
#define CP_COMMIT() asm volatile("cp.async.commit_group;" ::: "memory")
#define CP_WAIT2()  asm volatile("cp.async.wait_group 2;" ::: "memory")
#define CP_WAIT1()  asm volatile("cp.async.wait_group 1;" ::: "memory")
#define CP_WAIT0()  asm volatile("cp.async.wait_group 0;" ::: "memory")

// one 32-wide K chunk of A and B into stage slot (per thread: one full A row
// segment (64B) + one full B row segment (64B); 128 threads cover 128 rows each)
__device__ __forceinline__ void issue32(uint32_t smb, int slot,
                                        const __nv_bfloat16* pa, const __nv_bfloat16* pb,
                                        uint32_t throff) {
    uint32_t so = smb + (uint32_t)slot * STAGEB2 + throff;
    cpasync16(so,      pa);      cpasync16(so + 16, pa + 8);
    cpasync16(so + 32, pa + 16); cpasync16(so + 48, pa + 24);
    uint32_t sb = so + OPB;
    cpasync16(sb,      pb);      cpasync16(sb + 16, pb + 8);
    cpasync16(sb + 32, pb + 16); cpasync16(sb + 48, pb + 24);
    CP_COMMIT();
}

// 128x128 mainloop, 128 threads, 4 warps (2x2), warp tile 64x64.
// Ath/Bth: per-thread row pointers (row = tid).
__device__ __forceinline__ void mma_tile_loop(uint32_t smb,
        const __nv_bfloat16* Ath, const __nv_bfloat16* Bth,
        int NCH, int tid, float acc[4][8][4]) {
    int lane = tid & 31, w = tid >> 5;
    int wm = w >> 1, wn = w & 1;
    uint32_t throff = (uint32_t)tid * SROWB;
    uint32_t aoff = (uint32_t)((wm * 64 + (lane & 15)) * SROWB + (lane >> 4) * 16);
    uint32_t boff = (uint32_t)((wn * 64 + (lane & 15)) * SROWB + (lane >> 4) * 16);

    issue32(smb, 0, Ath,              Bth,              throff);
    issue32(smb, 1, Ath + KCHUNK,     Bth + KCHUNK,     throff);
    issue32(smb, 2, Ath + 2 * KCHUNK, Bth + 2 * KCHUNK, throff);

    for (int kc = 0; kc < NCH; kc++) {
        if (kc + 2 < NCH)      CP_WAIT2();
        else if (kc + 1 < NCH) CP_WAIT1();
        else                   CP_WAIT0();
        __syncthreads();
        if (kc + 3 < NCH)
            issue32(smb, (kc + 3) & 3, Ath + (size_t)(kc + 3) * KCHUNK,
                    Bth + (size_t)(kc + 3) * KCHUNK, throff);

        uint32_t sb = smb + (uint32_t)(kc & 3) * STAGEB2;
        uint32_t aB = sb + aoff;
        uint32_t bB = sb + OPB + boff;
        #pragma unroll
        for (int ks = 0; ks < 2; ks++) {
            uint32_t koff = ks * 32;
            uint32_t af[4][4];
            #pragma unroll
            for (int mi = 0; mi < 4; mi++)
                ldmat4(af[mi][0], af[mi][1], af[mi][2], af[mi][3],
                       aB + mi * 16 * SROWB + koff);
            uint32_t bf_[4][4];
            #pragma unroll
            for (int nj = 0; nj < 4; nj++)
                ldmat4(bf_[nj][0], bf_[nj][1], bf_[nj][2], bf_[nj][3],
                       bB + nj * 16 * SROWB + koff);
            #pragma unroll
            for (int mi = 0; mi < 4; mi++)
                #pragma unroll
                for (int ni = 0; ni < 8; ni++) {
                    int nj = ni >> 1, p = ni & 1;
                    mma16816(acc[mi][ni], af[mi], bf_[nj][p], bf_[nj][p + 2]);
                }
        }
    }
}

// ---------------- dense GEMM -------------------------------------------------
__global__ void __launch_bounds__(128, 2) gemm_bf16(const __nv_bfloat16* __restrict__ A2,
                                                    const __nv_bfloat16* __restrict__ B2,
                                                    float* __restrict__ C, int ldc) {
    extern __shared__ __align__(16) char dynsm[];
    uint32_t smb = smem_u32(dynsm);
    int tid = threadIdx.x, lane = tid & 31, w = tid >> 5;
    int wm = w >> 1, wn = w & 1;
    int m0 = blockIdx.y * 128, n0 = blockIdx.x * 128;

    const __nv_bfloat16* Ath = A2 + (size_t)(m0 + tid) * KSPLIT;
    const __nv_bfloat16* Bth = B2 + (size_t)(n0 + tid) * KSPLIT;

    float acc[4][8][4] = {};
    mma_tile_loop(smb, Ath, Bth, KSPLIT / KCHUNK, tid, acc);

    #pragma unroll
    for (int mi = 0; mi < 4; mi++)
        #pragma unroll
        for (int ni = 0; ni < 8; ni++) {
            int r = m0 + wm * 64 + mi * 16 + (lane >> 2);
            int c = n0 + wn * 64 + ni * 8 + (lane & 3) * 2;
            float2 w0 = { acc[mi][ni][0], acc[mi][ni][1] };
            float2 w1 = { acc[mi][ni][2], acc[mi][ni][3] };
            *(float2*)(C + (size_t)r * ldc + c)       = w0;
            *(float2*)(C + (size_t)(r + 8) * ldc + c) = w1;
        }
}

// ---------------- RoPE -> split bf16 Q2/K2 ----------------------------------
__global__ void __launch_bounds__(128) rope_kernel() {
    __shared__ uint32_t sm[64][97];
    int bh = blockIdx.y;
    int b = bh >> 4, h = bh & 15;
    int s0 = blockIdx.x * 64;
    int t = threadIdx.x;

    float rq[64], rk[64];
    if (t < 64) {
        int s = s0 + t;
        const float* qp = g_qkv + (size_t)(b * SEQ + s) * QKVDIM + h * HEADD;
        const float* kp = qp + HIDDEN;
        float c[32], sn[32];
        const float LOG_TH = 9.210340371976184f;
        #pragma unroll
        for (int j = 0; j < 32; j++) {
            float freq = __expf(-(float)j * (LOG_TH / 32.0f));
            sincosf((float)s * freq, &sn[j], &c[j]);
        }
        float oq[64], ok[64];
        #pragma unroll
        for (int i = 0; i < 64; i++) { oq[i] = qp[i]; ok[i] = kp[i]; }
        #pragma unroll
        for (int j = 0; j < 32; j++) {
            rq[2*j]   = oq[2*j]   * c[j] - oq[32+j] * sn[j];
            rq[2*j+1] = oq[2*j+1] * c[j] + oq[j]    * sn[j];
            rk[2*j]   = ok[2*j]   * c[j] - ok[32+j] * sn[j];
            rk[2*j+1] = ok[2*j+1] * c[j] + ok[j]    * sn[j];
        }
    }

    if (t < 64) {
        #pragma unroll
        for (int j = 0; j < 32; j++) {
            uint32_t hp = pack_hi2(rq[2*j], rq[2*j+1]);
            sm[t][j]      = hp;
            sm[t][32 + j] = hp;
            sm[t][64 + j] = pack_lo2(rq[2*j], rq[2*j+1]);
        }
    }
    __syncthreads();
    {
        uint32_t* dst = (uint32_t*)(g_q2 + ((size_t)bh * SEQ + s0) * KQK);
        for (int idx = t; idx < 64 * 96; idx += 128) {
            int r = idx / 96, cidx = idx % 96;
            dst[r * 96 + cidx] = sm[r][cidx];
        }
    }
    __syncthreads();

    if (t < 64) {
        #pragma unroll
        for (int j = 0; j < 32; j++) {
            uint32_t hp = pack_hi2(rk[2*j], rk[2*j+1]);
            sm[t][j]      = hp;
            sm[t][32 + j] = pack_lo2(rk[2*j], rk[2*j+1]);
            sm[t][64 + j] = hp;
        }
    }
    __syncthreads();
    {
        uint32_t* dst = (uint32_t*)(g_k2 + ((size_t)bh * SEQ + s0) * KQK);
        for (int idx = t; idx < 64 * 96; idx += 128) {
            int r = idx / 96, cidx = idx % 96;
            dst[r * 96 + cidx] = sm[r][cidx];
        }
    }
}

// ---------------- scores (mma, causal) --------------------------------------
__global__ void __launch_bounds__(128, 2) scores_kernel(const __nv_bfloat16* __restrict__ Q2,
                                                        const __nv_bfloat16* __restrict__ K2,
                                                        float* __restrict__ probs) {
    int nt = blockIdx.x;
    int mt = 15 - (int)blockIdx.y;
    int bh = blockIdx.z;
    int m0 = mt * 128, n0 = nt * 128;
    int tid = threadIdx.x, lane = tid & 31, w = tid >> 5;
    int wm = w >> 1, wn = w & 1;

    if (nt > mt) {
        float4 z = {0.f, 0.f, 0.f, 0.f};
        float* base = probs + ((size_t)bh * SEQ + m0 + tid) * SEQ + n0;
        #pragma unroll
        for (int j = 0; j < 32; j++) *(float4*)(base + j * 4) = z;
        return;
    }

    extern __shared__ __align__(16) char dynsm[];
    uint32_t smb = smem_u32(dynsm);
    const __nv_bfloat16* Ath = Q2 + ((size_t)bh * SEQ + m0 + tid) * KQK;
    const __nv_bfloat16* Bth = K2 + ((size_t)bh * SEQ + n0 + tid) * KQK;

    float acc[4][8][4] = {};
    mma_tile_loop(smb, Ath, Bth, KQK / KCHUNK, tid, acc);

    float* pb = probs + (size_t)bh * SEQ * SEQ;
    if (nt < mt) {
        #pragma unroll
        for (int mi = 0; mi < 4; mi++)
            #pragma unroll
            for (int ni = 0; ni < 8; ni++) {
                int r = m0 + wm * 64 + mi * 16 + (lane >> 2);
                int c = n0 + wn * 64 + ni * 8 + (lane & 3) * 2;
                float2 w0 = { acc[mi][ni][0]*ATT_SCALE, acc[mi][ni][1]*ATT_SCALE };
                float2 w1 = { acc[mi][ni][2]*ATT_SCALE, acc[mi][ni][3]*ATT_SCALE };
                *(float2*)(pb + (size_t)r * SEQ + c)       = w0;
                *(float2*)(pb + (size_t)(r + 8) * SEQ + c) = w1;
            }
    } else {
        #pragma unroll
        for (int mi = 0; mi < 4; mi++)
            #pragma unroll
            for (int ni = 0; ni < 8; ni++) {
                int r = m0 + wm * 64 + mi * 16 + (lane >> 2);
                int c = n0 + wn * 64 + ni * 8 + (lane & 3) * 2;
                pb[(size_t)r * SEQ + c]         = (c     <= r)     ? acc[mi][ni][0]*ATT_SCALE : 0.f;
                pb[(size_t)r * SEQ + c + 1]     = (c + 1 <= r)     ? acc[mi][ni][1]*ATT_SCALE : 0.f;
                pb[(size_t)(r+8) * SEQ + c]     = (c     <= r + 8) ? acc[mi][ni][2]*ATT_SCALE : 0.f;
                pb[(size_t)(r+8) * SEQ + c + 1] = (c + 1 <= r + 8) ? acc[mi][ni][3]*ATT_SCALE : 0.f;
            }
    }
}

// ---------------- row softmax ------------------------------------------------
__global__ void softmax_kernel(float* __restrict__ probs) {
    int bh = blockIdx.y;
    int row = blockIdx.x;
    float* p = probs + ((size_t)bh * SEQ + row) * SEQ;
    int len = row + 1;
    int t = threadIdx.x;

    __shared__ float buf[SEQ];
    __shared__ float red[8];

    float mx = -3.4e38f;
    int n4 = len >> 2;
    const float4* p4 = (const float4*)p;
    float4* b4 = (float4*)buf;
    for (int i = t; i < n4; i += 256) {
        float4 v = p4[i]; b4[i] = v;
        mx = fmaxf(mx, fmaxf(fmaxf(v.x, v.y), fmaxf(v.z, v.w)));
    }
    for (int i = (n4 << 2) + t; i < len; i += 256) { float v = p[i]; buf[i] = v; mx = fmaxf(mx, v); }
    #pragma unroll
    for (int o = 16; o > 0; o >>= 1) mx = fmaxf(mx, __shfl_xor_sync(0xffffffffu, mx, o));
    if ((t & 31) == 0) red[t >> 5] = mx;
    __syncthreads();
    mx = red[0];
    #pragma unroll
    for (int i = 1; i < 8; i++) mx = fmaxf(mx, red[i]);
    __syncthreads();

    float sum = 0.f;
    for (int i = t; i < len; i += 256) { float e = __expf(buf[i] - mx); buf[i] = e; sum += e; }
    #pragma unroll
    for (int o = 16; o > 0; o >>= 1) sum += __shfl_xor_sync(0xffffffffu, sum, o);
    if ((t & 31) == 0) red[t >> 5] = sum;
    __syncthreads();
    float tot = 0.f;
    #pragma unroll
    for (int i = 0; i < 8; i++) tot += red[i];
    float inv = 1.0f / tot;

    float4* o4 = (float4*)p;
    for (int i = t; i < n4; i += 256) {
        float4 v = b4[i];
        v.x *= inv; v.y *= inv; v.z *= inv; v.w *= inv;
        o4[i] = v;
    }
    for (int i = (n4 << 2) + t; i < len; i += 256) p[i] = buf[i] * inv;
}

// ---------------- PV via mma (split bf16, 3-term) ----------------------------
__global__ void __launch_bounds__(256) pv_kernel(const float* __restrict__ probs) {
    __shared__ __align__(16) __nv_bfloat16 Phi[128 * 40];
    __shared__ __align__(16) __nv_bfloat16 Plo[128 * 40];
    __shared__ __align__(16) __nv_bfloat16 Vhi[32 * 72];
    __shared__ __align__(16) __nv_bfloat16 Vlo[32 * 72];

    int bh = blockIdx.y;
    int mt = (int)gridDim.x - 1 - (int)blockIdx.x;
    int b = bh >> 4, h = bh & 15;
    int m0 = mt * 128;
    int tid = threadIdx.x, lane = tid & 31, w = tid >> 5;
    int wm = w >> 1, wn = w & 1;

    int prow = tid >> 1, pseg = (tid & 1) * 16;
    int vrow = tid >> 3, vseg = (tid & 7) * 8;
    const float* Pg = probs + ((size_t)bh * SEQ + m0 + prow) * SEQ + pseg;
    const float* Vg = g_qkv + (size_t)(b * SEQ + vrow) * QKVDIM + 2 * HIDDEN + h * HEADD + vseg;

    float acc[2][4][4] = {};

    uint32_t phiB = smem_u32(Phi) + (uint32_t)((wm * 32 + (lane & 15)) * 80 + (lane >> 4) * 16);
    uint32_t ploB = smem_u32(Plo) + (uint32_t)((wm * 32 + (lane & 15)) * 80 + (lane >> 4) * 16);
    uint32_t vhiB = smem_u32(Vhi) + (uint32_t)(wn * 64 + (lane & 15) * 144 + (lane >> 4) * 16);
    uint32_t vloB = smem_u32(Vlo) + (uint32_t)(wn * 64 + (lane & 15) * 144 + (lane >> 4) * 16);

    int NCH = (mt + 1) * 4;
    float4 p0 = *(const float4*)(Pg);     float4 p1 = *(const float4*)(Pg + 4);
    float4 p2 = *(const float4*)(Pg + 8); float4 p3 = *(const float4*)(Pg + 12);
    float4 v0 = *(const float4*)(Vg);     float4 v1 = *(const float4*)(Vg + 4);

    for (int kc = 0; kc < NCH; kc++) {
        {
            float pv[16] = {p0.x,p0.y,p0.z,p0.w, p1.x,p1.y,p1.z,p1.w,
                            p2.x,p2.y,p2.z,p2.w, p3.x,p3.y,p3.z,p3.w};
            uint32_t hw[8], lw[8];
            #pragma unroll
            for (int i = 0; i < 8; i++) {
                hw[i] = pack_hi2(pv[2*i], pv[2*i+1]);
                lw[i] = pack_lo2(pv[2*i], pv[2*i+1]);
            }
            uint32_t off = (uint32_t)(prow * 80 + pseg * 2);
            *(uint4*)((char*)Phi + off)      = make_uint4(hw[0], hw[1], hw[2], hw[3]);
            *(uint4*)((char*)Phi + off + 16) = make_uint4(hw[4], hw[5], hw[6], hw[7]);
            *(uint4*)((char*)Plo + off)      = make_uint4(lw[0], lw[1], lw[2], lw[3]);
            *(uint4*)((char*)Plo + off + 16) = make_uint4(lw[4], lw[5], lw[6], lw[7]);

            float vv[8] = {v0.x,v0.y,v0.z,v0.w, v1.x,v1.y,v1.z,v1.w};
            uint32_t vh[4], vl[4];
            #pragma unroll
            for (int i = 0; i < 4; i++) {
                vh[i] = pack_hi2(vv[2*i], vv[2*i+1]);
                vl[i] = pack_lo2(vv[2*i], vv[2*i+1]);
            }
            uint32_t voff = (uint32_t)(vrow * 144 + vseg * 2);
            *(uint4*)((char*)Vhi + voff) = make_uint4(vh[0], vh[1], vh[2], vh[3]);
            *(uint4*)((char*)Vlo + voff) = make_uint4(vl[0], vl[1], vl[2], vl[3]);
        }
        __syncthreads();
        if (kc + 1 < NCH) {
            const float* Pn = Pg + (size_t)(kc + 1) * 32;
            p0 = *(const float4*)(Pn);     p1 = *(const float4*)(Pn + 4);
            p2 = *(const float4*)(Pn + 8); p3 = *(const float4*)(Pn + 12);
            const float* Vn = Vg + (size_t)(kc + 1) * 32 * QKVDIM;
            v0 = *(const float4*)(Vn);     v1 = *(const float4*)(Vn + 4);
        }
        #pragma unroll
        for (int ks = 0; ks < 2; ks++) {
            uint32_t pk = ks * 32;
            uint32_t vk = ks * 16 * 144;
            uint32_t ahi[2][4], alo[2][4];
            ldmat4(ahi[0][0], ahi[0][1], ahi[0][2], ahi[0][3], phiB + pk);
            ldmat4(ahi[1][0], ahi[1][1], ahi[1][2], ahi[1][3], phiB + 16 * 80 + pk);
            ldmat4(alo[0][0], alo[0][1], alo[0][2], alo[0][3], ploB + pk);
            ldmat4(alo[1][0], alo[1][1], alo[1][2], alo[1][3], ploB + 16 * 80 + pk);
            uint32_t bh_[2][4], bl_[2][4];
            ldmat4t(bh_[0][0], bh_[0][1], bh_[0][2], bh_[0][3], vhiB + vk);
            ldmat4t(bh_[1][0], bh_[1][1], bh_[1][2], bh_[1][3], vhiB + vk + 32);
            ldmat4t(bl_[0][0], bl_[0][1], bl_[0][2], bl_[0][3], vloB + vk);
            ldmat4t(bl_[1][0], bl_[1][1], bl_[1][2], bl_[1][3], vloB + vk + 32);
            #pragma unroll
            for (int mi = 0; mi < 2; mi++)
                #pragma unroll
                for (int hf = 0; hf < 2; hf++)
                    #pragma unroll
                    for (int oc = 0; oc < 2; oc++) {
                        int oct = hf * 2 + oc;
                        mma16816(acc[mi][oct], ahi[mi], bh_[hf][oc*2], bh_[hf][oc*2+1]);
                        mma16816(acc[mi][oct], ahi[mi], bl_[hf][oc*2], bl_[hf][oc*2+1]);
                        mma16816(acc[mi][oct], alo[mi], bh_[hf][oc*2], bh_[hf][oc*2+1]);
                    }
        }
        __syncthreads();
    }

    #pragma unroll
    for (int mi = 0; mi < 2; mi++)
        #pragma unroll
        for (int oct = 0; oct < 4; oct++) {
            int r = m0 + wm * 32 + mi * 16 + (lane >> 2);
            int c = h * HEADD + wn * 32 + oct * 8 + (lane & 3) * 2;
            __nv_bfloat16* row0 = g_attn2 + (size_t)(b * SEQ + r) * KSPLIT;
            __nv_bfloat16* row1 = g_attn2 + (size_t)(b * SEQ + r + 8) * KSPLIT;
            store_split2(row0, c, acc[mi][oct][0], acc[mi][oct][1]);
            store_split2(row1, c, acc[mi][oct][2], acc[mi][oct][3]);
        }
}

// ---------------------------------------------------------------------------
extern "C" void kernel_launch(void* const* d_in, const int* in_sizes, int n_in,
                              void* d_out, int out_size) {
    const float* hs    = (const float*)d_in[0];
    const float* Wqkv  = (const float*)d_in[1];
    const float* Wout  = (const float*)d_in[2];
    const float* gamma = (const float*)d_in[3];
    const float* beta  = (const float*)d_in[4];

    float* out = (float*)d_out;
    const size_t OUT_ELEMS   = (size_t)MROWS * HIDDEN;
    const size_t PROBS_ELEMS = (size_t)BATCH * NHEADS * SEQ * SEQ;

    float* probs;
    if ((size_t)out_size >= OUT_ELEMS + PROBS_ELEMS) {
        probs = out + OUT_ELEMS;
    } else {
        void* p; cudaGetSymbolAddress(&p, g_probs_fb);
        probs = (float*)p;
    }

    void* pq;  cudaGetSymbolAddress(&pq, g_qkv);
    void* pa2; cudaGetSymbolAddress(&pa2, g_a2);
    void* pw1; cudaGetSymbolAddress(&pw1, g_wqkv2);
    void* pw2; cudaGetSymbolAddress(&pw2, g_wout2);
    void* pat; cudaGetSymbolAddress(&pat, g_attn2);
    void* pq2; cudaGetSymbolAddress(&pq2, g_q2);
    void* pk2; cudaGetSymbolAddress(&pk2, g_k2);
    float* qkv = (float*)pq;
    __nv_bfloat16* a2  = (__nv_bfloat16*)pa2;
    __nv_bfloat16* w1  = (__nv_bfloat16*)pw1;
    __nv_bfloat16* w2  = (__nv_bfloat16*)pw2;
    __nv_bfloat16* at2 = (__nv_bfloat16*)pat;
    __nv_bfloat16* q2  = (__nv_bfloat16*)pq2;
    __nv_bfloat16* k2  = (__nv_bfloat16*)pk2;

    static int smem_set = 0;
    if (!smem_set) {
        cudaFuncSetAttribute(gemm_bf16, cudaFuncAttributeMaxDynamicSharedMemorySize, DYNSM);
        cudaFuncSetAttribute(scores_kernel, cudaFuncAttributeMaxDynamicSharedMemorySize, DYNSM);
        smem_set = 1;
    }

    ln_kernel<<<MROWS, 256>>>(hs, gamma, beta);
    conv_w<<<(QKVDIM * HIDDEN / 4 + 255) / 256, 256>>>(Wqkv, w1, QKVDIM * HIDDEN);
    conv_w<<<(HIDDEN * HIDDEN / 4 + 255) / 256, 256>>>(Wout, w2, HIDDEN * HIDDEN);

    gemm_bf16<<<dim3(QKVDIM / 128, MROWS / 128), 128, DYNSM>>>(a2, w1, qkv, QKVDIM);

    rope_kernel<<<dim3(SEQ / 64, BATCH * NHEADS), 128>>>();

    scores_kernel<<<dim3(SEQ / 128, SEQ / 128, BATCH * NHEADS), 128, DYNSM>>>(q2, k2, probs);

    softmax_kernel<<<dim3(SEQ, BATCH * NHEADS), 256>>>(probs);

    pv_kernel<<<dim3(SEQ / 128, BATCH * NHEADS), 256>>>(probs);

    gemm_bf16<<<dim3(HIDDEN / 128, MROWS / 128), 128, DYNSM>>>(at2, w2, out, HIDDEN);
}

// round 9
// speedup vs baseline: 1.1858x; 1.1858x over previous
#include <cuda_runtime.h>
#include <cuda_bf16.h>
#include <cstdint>
#include <math.h>

#define BATCH   2
#define SEQ     2048
#define HIDDEN  1024
#define NHEADS  16
#define HEADD   64
#define MROWS   (BATCH*SEQ)      // 4096
#define QKVDIM  (3*HIDDEN)       // 3072
#define KSPLIT  3072             // K' for dense GEMMs
#define KQK     192              // K' for scores (3*64)
#define ATT_SCALE 0.125f
#define LNEPS   1e-5f

// ---------------- scratch (static device memory) ---------------------------
__device__ __nv_bfloat16 g_a2[(size_t)MROWS * KSPLIT];
__device__ __nv_bfloat16 g_wqkv2[(size_t)QKVDIM * KSPLIT];
__device__ __nv_bfloat16 g_wout2[(size_t)HIDDEN * KSPLIT];
__device__ __nv_bfloat16 g_attn2[(size_t)MROWS * KSPLIT];
__device__ float g_qkv[(size_t)MROWS * QKVDIM];
__device__ __nv_bfloat16 g_q2[(size_t)BATCH * NHEADS * SEQ * KQK];
__device__ __nv_bfloat16 g_k2[(size_t)BATCH * NHEADS * SEQ * KQK];
__device__ float g_probs_fb[(size_t)BATCH * NHEADS * SEQ * SEQ];

__device__ __forceinline__ uint32_t smem_u32(const void* p) {
    uint32_t a;
    asm("{ .reg .u64 t; cvta.to.shared.u64 t, %1; cvt.u32.u64 %0, t; }" : "=r"(a) : "l"(p));
    return a;
}

// ---------------- bf16 split helpers ----------------------------------------
__device__ __forceinline__ unsigned short bfb(float v) {
    __nv_bfloat16 h = __float2bfloat16(v);
    return *(unsigned short*)&h;
}
__device__ __forceinline__ float bf2f(unsigned short u) {
    __nv_bfloat16 h = *(__nv_bfloat16*)&u;
    return __bfloat162float(h);
}
__device__ __forceinline__ uint32_t pack_hi2(float a, float b) {
    return (uint32_t)bfb(a) | ((uint32_t)bfb(b) << 16);
}
__device__ __forceinline__ uint32_t pack_lo2(float a, float b) {
    unsigned short ha = bfb(a), hb = bfb(b);
    return (uint32_t)bfb(a - bf2f(ha)) | ((uint32_t)bfb(b - bf2f(hb)) << 16);
}
__device__ __forceinline__ void store_split4(__nv_bfloat16* rowbase, int k,
                                             float v0, float v1, float v2, float v3) {
    uint2 hw = { pack_hi2(v0, v1), pack_hi2(v2, v3) };
    uint2 lw = { pack_lo2(v0, v1), pack_lo2(v2, v3) };
    *(uint2*)(rowbase + k)        = hw;
    *(uint2*)(rowbase + 1024 + k) = hw;
    *(uint2*)(rowbase + 2048 + k) = lw;
}
__device__ __forceinline__ void store_split2(__nv_bfloat16* rowbase, int k, float a, float b) {
    uint32_t hw = pack_hi2(a, b), lw = pack_lo2(a, b);
    *(uint32_t*)(rowbase + k)        = hw;
    *(uint32_t*)(rowbase + 1024 + k) = hw;
    *(uint32_t*)(rowbase + 2048 + k) = lw;
}

// ---------------- LayerNorm -> split bf16 -----------------------------------
__global__ void ln_kernel(const float* __restrict__ hs,
                          const float* __restrict__ gamma,
                          const float* __restrict__ beta) {
    int row = blockIdx.x;
    int t = threadIdx.x;
    const float4* x4 = (const float4*)(hs + (size_t)row * HIDDEN);
    float4 v = x4[t];
    float s  = v.x + v.y + v.z + v.w;
    float sq = v.x*v.x + v.y*v.y + v.z*v.z + v.w*v.w;
    #pragma unroll
    for (int o = 16; o > 0; o >>= 1) {
        s  += __shfl_xor_sync(0xffffffffu, s,  o);
        sq += __shfl_xor_sync(0xffffffffu, sq, o);
    }
    __shared__ float ss[8], ssq[8];
    if ((t & 31) == 0) { ss[t >> 5] = s; ssq[t >> 5] = sq; }
    __syncthreads();
    float tot = 0.f, totq = 0.f;
    #pragma unroll
    for (int i = 0; i < 8; i++) { tot += ss[i]; totq += ssq[i]; }
    float mean = tot * (1.0f / HIDDEN);
    float var  = totq * (1.0f / HIDDEN) - mean * mean;
    float inv  = rsqrtf(var + LNEPS);

    float4 g = ((const float4*)gamma)[t];
    float4 b = ((const float4*)beta)[t];
    float o0 = (v.x - mean) * inv * g.x + b.x;
    float o1 = (v.y - mean) * inv * g.y + b.y;
    float o2 = (v.z - mean) * inv * g.z + b.z;
    float o3 = (v.w - mean) * inv * g.w + b.w;
    store_split4(g_a2 + (size_t)row * KSPLIT, t * 4, o0, o1, o2, o3);
}

// ---------------- weight conversion -----------------------------------------
__global__ void conv_w(const float* __restrict__ W, __nv_bfloat16* __restrict__ W2, int total) {
    int gid = blockIdx.x * blockDim.x + threadIdx.x;
    int i4 = gid * 4;
    if (i4 >= total) return;
    int n = i4 >> 10, k = i4 & 1023;
    float4 w = *(const float4*)(W + i4);
    uint2 hw = { pack_hi2(w.x, w.y), pack_hi2(w.z, w.w) };
    uint2 lw = { pack_lo2(w.x, w.y), pack_lo2(w.z, w.w) };
    __nv_bfloat16* rb = W2 + (size_t)n * KSPLIT;
    *(uint2*)(rb + k)        = hw;
    *(uint2*)(rb + 1024 + k) = lw;
    *(uint2*)(rb + 2048 + k) = hw;
}

// ---------------- mma plumbing ----------------------------------------------
#define SROWB   80         // bytes per smem row (32 bf16 + 8 pad)
#define KCHUNK  32
#define STAGES  5
#define OPB     (128 * SROWB)      // 10240
#define STAGEB2 (2 * OPB)          // 20480
#define DYNSM   (STAGES * STAGEB2) // 102400 (5 stages)

__device__ __forceinline__ void ldmat4(uint32_t& r0, uint32_t& r1,
                                       uint32_t& r2, uint32_t& r3, uint32_t addr) {
    asm volatile("ldmatrix.sync.aligned.m8n8.x4.shared.b16 {%0,%1,%2,%3}, [%4];"
                 : "=r"(r0), "=r"(r1), "=r"(r2), "=r"(r3) : "r"(addr));
}
__device__ __forceinline__ void ldmat4t(uint32_t& r0, uint32_t& r1,
                                        uint32_t& r2, uint32_t& r3, uint32_t addr) {
    asm volatile("ldmatrix.sync.aligned.m8n8.x4.trans.shared.b16 {%0,%1,%2,%3}, [%4];"
                 : "=r"(r0), "=r"(r1), "=r"(r2), "=r"(r3) : "r"(addr));
}
__device__ __forceinline__ void mma16816(float* c, const uint32_t* a, uint32_t b0, uint32_t b1) {
    asm volatile("mma.sync.aligned.m16n8k16.row.col.f32.bf16.bf16.f32 "
                 "{%0,%1,%2,%3}, {%4,%5,%6,%7}, {%8,%9}, {%0,%1,%2,%3};"
                 : "+f"(c[0]), "+f"(c[1]), "+f"(c[2]), "+f"(c[3])
                 : "r"(a[0]), "r"(a[1]), "r"(a[2]), "r"(a[3]), "r"(b0), "r"(b1));
}
__device__ __forceinline__ void cpasync16(uint32_t s, const void* g) {
    asm volatile("cp.async.cg.shared.global [%0], [%1], 16;" :: "r"(s), "l"(g));
}
#define CP_COMMIT() asm volatile("cp.async.commit_group;" ::: "memory")
#define CP_WAIT3()  asm volatile("cp.async.wait_group 3;" ::: "memory")
#define CP_WAIT2()  asm volatile("cp.async.wait_group 2;" ::: "memory")
#define CP_WAIT1()  asm volatile("cp.async.wait_group 1;" ::: "memory")
#define CP_WAIT0()  asm volatile("cp.async.wait_group 0;" ::: "memory")

// one 32-wide K chunk of A and B into stage slot (per-thread: 32B A + 32B B)
__device__ __forceinline__ void issue32(uint32_t smb, int slot,
                                        const __nv_bfloat16* pa, const __nv_bfloat16* pb,
                                        uint32_t throff) {
    uint32_t so = smb + (uint32_t)slot * STAGEB2 + throff;
    cpasync16(so,      pa); cpasync16(so + 16, pa + 8);
    uint32_t sb = so + OPB;
    cpasync16(sb,      pb); cpasync16(sb + 16, pb + 8);
    CP_COMMIT();
}

// shared 128x128 mainloop, 256 threads, 8 warps (4m x 2n), warp tile 32x64.
// Ath/Bth: per-thread pointers (row=tid>>1, half=tid&1).
__device__ __forceinline__ void mma_tile_loop(uint32_t smb,
        const __nv_bfloat16* Ath, const __nv_bfloat16* Bth,
        int NCH, int tid, float acc[2][8][4]) {
    int lane = tid & 31, w = tid >> 5;
    int wm = w >> 1, wn = w & 1;
    uint32_t throff = (uint32_t)((tid >> 1) * SROWB + (tid & 1) * 32);
    uint32_t aoff = (uint32_t)((wm * 32 + (lane & 15)) * SROWB + (lane >> 4) * 16);
    uint32_t boff = (uint32_t)((wn * 64 + (lane & 15)) * SROWB + (lane >> 4) * 16);

    issue32(smb, 0, Ath,              Bth,              throff);
    issue32(smb, 1, Ath + KCHUNK,     Bth + KCHUNK,     throff);
    issue32(smb, 2, Ath + 2 * KCHUNK, Bth + 2 * KCHUNK, throff);
    issue32(smb, 3, Ath + 3 * KCHUNK, Bth + 3 * KCHUNK, throff);

    for (int kc = 0; kc < NCH; kc++) {
        if (kc + 3 < NCH)      CP_WAIT3();
        else if (kc + 2 < NCH) CP_WAIT2();
        else if (kc + 1 < NCH) CP_WAIT1();
        else                   CP_WAIT0();
        __syncthreads();
        // slot (kc+4)%5 was chunk kc-1's; its compute finished before this barrier
        if (kc + 4 < NCH)
            issue32(smb, (kc + 4) % STAGES, Ath + (size_t)(kc + 4) * KCHUNK,
                    Bth + (size_t)(kc + 4) * KCHUNK, throff);

        uint32_t sb = smb + (uint32_t)(kc % STAGES) * STAGEB2;
        uint32_t aB = sb + aoff;
        uint32_t bB = sb + OPB + boff;
        #pragma unroll
        for (int ks = 0; ks < 2; ks++) {
            uint32_t koff = ks * 32;
            uint32_t af[2][4];
            ldmat4(af[0][0], af[0][1], af[0][2], af[0][3], aB + koff);
            ldmat4(af[1][0], af[1][1], af[1][2], af[1][3], aB + 16 * SROWB + koff);
            uint32_t bf_[4][4];
            #pragma unroll
            for (int n2 = 0; n2 < 4; n2++)
                ldmat4(bf_[n2][0], bf_[n2][1], bf_[n2][2], bf_[n2][3],
                       bB + n2 * 16 * SROWB + koff);
            #pragma unroll
            for (int mi = 0; mi < 2; mi++)
                #pragma unroll
                for (int ni = 0; ni < 8; ni++) {
                    int n2 = ni >> 1, p = ni & 1;
                    mma16816(acc[mi][ni], af[mi], bf_[n2][p], bf_[n2][p + 2]);
                }
        }
    }
}

// ---------------- dense GEMM -------------------------------------------------
__global__ void __launch_bounds__(256, 2) gemm_bf16(const __nv_bfloat16* __restrict__ A2,
                                                    const __nv_bfloat16* __restrict__ B2,
                                                    float* __restrict__ C, int ldc) {
    extern __shared__ __align__(16) char dynsm[];
    uint32_t smb = smem_u32(dynsm);
    int tid = threadIdx.x, lane = tid & 31, w = tid >> 5;
    int wm = w >> 1, wn = w & 1;
    int m0 = blockIdx.y * 128, n0 = blockIdx.x * 128;
    int row = tid >> 1, half = tid & 1;

    const __nv_bfloat16* Ath = A2 + (size_t)(m0 + row) * KSPLIT + half * 16;
    const __nv_bfloat16* Bth = B2 + (size_t)(n0 + row) * KSPLIT + half * 16;

    float acc[2][8][4] = {};
    mma_tile_loop(smb, Ath, Bth, KSPLIT / KCHUNK, tid, acc);

    #pragma unroll
    for (int mi = 0; mi < 2; mi++)
        #pragma unroll
        for (int ni = 0; ni < 8; ni++) {
            int r = m0 + wm * 32 + mi * 16 + (lane >> 2);
            int c = n0 + wn * 64 + ni * 8 + (lane & 3) * 2;
            float2 w0 = { acc[mi][ni][0], acc[mi][ni][1] };
            float2 w1 = { acc[mi][ni][2], acc[mi][ni][3] };
            *(float2*)(C + (size_t)r * ldc + c)       = w0;
            *(float2*)(C + (size_t)(r + 8) * ldc + c) = w1;
        }
}

// ---------------- RoPE -> split bf16 Q2/K2 ----------------------------------
__global__ void __launch_bounds__(128) rope_kernel() {
    __shared__ uint32_t sm[64][97];
    int bh = blockIdx.y;
    int b = bh >> 4, h = bh & 15;
    int s0 = blockIdx.x * 64;
    int t = threadIdx.x;

    float rq[64], rk[64];
    if (t < 64) {
        int s = s0 + t;
        const float* qp = g_qkv + (size_t)(b * SEQ + s) * QKVDIM + h * HEADD;
        const float* kp = qp + HIDDEN;
        float c[32], sn[32];
        const float LOG_TH = 9.210340371976184f;
        #pragma unroll
        for (int j = 0; j < 32; j++) {
            float freq = __expf(-(float)j * (LOG_TH / 32.0f));
            sincosf((float)s * freq, &sn[j], &c[j]);
        }
        float oq[64], ok[64];
        #pragma unroll
        for (int i = 0; i < 64; i++) { oq[i] = qp[i]; ok[i] = kp[i]; }
        #pragma unroll
        for (int j = 0; j < 32; j++) {
            rq[2*j]   = oq[2*j]   * c[j] - oq[32+j] * sn[j];
            rq[2*j+1] = oq[2*j+1] * c[j] + oq[j]    * sn[j];
            rk[2*j]   = ok[2*j]   * c[j] - ok[32+j] * sn[j];
            rk[2*j+1] = ok[2*j+1] * c[j] + ok[j]    * sn[j];
        }
    }

    if (t < 64) {
        #pragma unroll
        for (int j = 0; j < 32; j++) {
            uint32_t hp = pack_hi2(rq[2*j], rq[2*j+1]);
            sm[t][j]      = hp;
            sm[t][32 + j] = hp;
            sm[t][64 + j] = pack_lo2(rq[2*j], rq[2*j+1]);
        }
    }
    __syncthreads();
    {
        uint32_t* dst = (uint32_t*)(g_q2 + ((size_t)bh * SEQ + s0) * KQK);
        for (int idx = t; idx < 64 * 96; idx += 128) {
            int r = idx / 96, cidx = idx % 96;
            dst[r * 96 + cidx] = sm[r][cidx];
        }
    }
    __syncthreads();

    if (t < 64) {
        #pragma unroll
        for (int j = 0; j < 32; j++) {
            uint32_t hp = pack_hi2(rk[2*j], rk[2*j+1]);
            sm[t][j]      = hp;
            sm[t][32 + j] = pack_lo2(rk[2*j], rk[2*j+1]);
            sm[t][64 + j] = hp;
        }
    }
    __syncthreads();
    {
        uint32_t* dst = (uint32_t*)(g_k2 + ((size_t)bh * SEQ + s0) * KQK);
        for (int idx = t; idx < 64 * 96; idx += 128) {
            int r = idx / 96, cidx = idx % 96;
            dst[r * 96 + cidx] = sm[r][cidx];
        }
    }
}

// ---------------- scores (mma, causal) --------------------------------------
__global__ void __launch_bounds__(256, 2) scores_kernel(const __nv_bfloat16* __restrict__ Q2,
                                                        const __nv_bfloat16* __restrict__ K2,
                                                        float* __restrict__ probs) {
    int nt = blockIdx.x;
    int mt = 15 - (int)blockIdx.y;
    int bh = blockIdx.z;
    int m0 = mt * 128, n0 = nt * 128;
    int tid = threadIdx.x, lane = tid & 31, w = tid >> 5;
    int wm = w >> 1, wn = w & 1;

    if (nt > mt) {
        int tx = tid & 15, ty = tid >> 4;
        float4 z = {0.f, 0.f, 0.f, 0.f};
        #pragma unroll
        for (int ih = 0; ih < 2; ih++)
            #pragma unroll
            for (int i = 0; i < 4; i++) {
                int rm = m0 + ty * 4 + ih * 64 + i;
                float* rowp = probs + ((size_t)bh * SEQ + rm) * SEQ + n0;
                *(float4*)(rowp + tx * 4)      = z;
                *(float4*)(rowp + tx * 4 + 64) = z;
            }
        return;
    }

    extern __shared__ __align__(16) char dynsm[];
    uint32_t smb = smem_u32(dynsm);
    int row = tid >> 1, half = tid & 1;
    const __nv_bfloat16* Ath = Q2 + ((size_t)bh * SEQ + m0 + row) * KQK + half * 16;
    const __nv_bfloat16* Bth = K2 + ((size_t)bh * SEQ + n0 + row) * KQK + half * 16;

    float acc[2][8][4] = {};
    mma_tile_loop(smb, Ath, Bth, KQK / KCHUNK, tid, acc);

    float* pb = probs + (size_t)bh * SEQ * SEQ;
    if (nt < mt) {
        #pragma unroll
        for (int mi = 0; mi < 2; mi++)
            #pragma unroll
            for (int ni = 0; ni < 8; ni++) {
                int r = m0 + wm * 32 + mi * 16 + (lane >> 2);
                int c = n0 + wn * 64 + ni * 8 + (lane & 3) * 2;
                float2 w0 = { acc[mi][ni][0]*ATT_SCALE, acc[mi][ni][1]*ATT_SCALE };
                float2 w1 = { acc[mi][ni][2]*ATT_SCALE, acc[mi][ni][3]*ATT_SCALE };
                *(float2*)(pb + (size_t)r * SEQ + c)       = w0;
                *(float2*)(pb + (size_t)(r + 8) * SEQ + c) = w1;
            }
    } else {
        #pragma unroll
        for (int mi = 0; mi < 2; mi++)
            #pragma unroll
            for (int ni = 0; ni < 8; ni++) {
                int r = m0 + wm * 32 + mi * 16 + (lane >> 2);
                int c = n0 + wn * 64 + ni * 8 + (lane & 3) * 2;
                pb[(size_t)r * SEQ + c]         = (c     <= r)     ? acc[mi][ni][0]*ATT_SCALE : 0.f;
                pb[(size_t)r * SEQ + c + 1]     = (c + 1 <= r)     ? acc[mi][ni][1]*ATT_SCALE : 0.f;
                pb[(size_t)(r+8) * SEQ + c]     = (c     <= r + 8) ? acc[mi][ni][2]*ATT_SCALE : 0.f;
                pb[(size_t)(r+8) * SEQ + c + 1] = (c + 1 <= r + 8) ? acc[mi][ni][3]*ATT_SCALE : 0.f;
            }
    }
}

// ---------------- row softmax ------------------------------------------------
__global__ void softmax_kernel(float* __restrict__ probs) {
    int bh = blockIdx.y;
    int row = blockIdx.x;
    float* p = probs + ((size_t)bh * SEQ + row) * SEQ;
    int len = row + 1;
    int t = threadIdx.x;

    __shared__ float buf[SEQ];
    __shared__ float red[8];

    float mx = -3.4e38f;
    int n4 = len >> 2;
    const float4* p4 = (const float4*)p;
    float4* b4 = (float4*)buf;
    for (int i = t; i < n4; i += 256) {
        float4 v = p4[i]; b4[i] = v;
        mx = fmaxf(mx, fmaxf(fmaxf(v.x, v.y), fmaxf(v.z, v.w)));
    }
    for (int i = (n4 << 2) + t; i < len; i += 256) { float v = p[i]; buf[i] = v; mx = fmaxf(mx, v); }
    #pragma unroll
    for (int o = 16; o > 0; o >>= 1) mx = fmaxf(mx, __shfl_xor_sync(0xffffffffu, mx, o));
    if ((t & 31) == 0) red[t >> 5] = mx;
    __syncthreads();
    mx = red[0];
    #pragma unroll
    for (int i = 1; i < 8; i++) mx = fmaxf(mx, red[i]);
    __syncthreads();

    float sum = 0.f;
    for (int i = t; i < len; i += 256) { float e = __expf(buf[i] - mx); buf[i] = e; sum += e; }
    #pragma unroll
    for (int o = 16; o > 0; o >>= 1) sum += __shfl_xor_sync(0xffffffffu, sum, o);
    if ((t & 31) == 0) red[t >> 5] = sum;
    __syncthreads();
    float tot = 0.f;
    #pragma unroll
    for (int i = 0; i < 8; i++) tot += red[i];
    float inv = 1.0f / tot;

    float4* o4 = (float4*)p;
    for (int i = t; i < n4; i += 256) {
        float4 v = b4[i];
        v.x *= inv; v.y *= inv; v.z *= inv; v.w *= inv;
        o4[i] = v;
    }
    for (int i = (n4 << 2) + t; i < len; i += 256) p[i] = buf[i] * inv;
}

// ---------------- PV via mma (split bf16, 3-term) ----------------------------
__global__ void __launch_bounds__(256) pv_kernel(const float* __restrict__ probs) {
    __shared__ __align__(16) __nv_bfloat16 Phi[128 * 40];
    __shared__ __align__(16) __nv_bfloat16 Plo[128 * 40];
    __shared__ __align__(16) __nv_bfloat16 Vhi[32 * 72];
    __shared__ __align__(16) __nv_bfloat16 Vlo[32 * 72];

    int bh = blockIdx.y;
    int mt = (int)gridDim.x - 1 - (int)blockIdx.x;
    int b = bh >> 4, h = bh & 15;
    int m0 = mt * 128;
    int tid = threadIdx.x, lane = tid & 31, w = tid >> 5;
    int wm = w >> 1, wn = w & 1;

    int prow = tid >> 1, pseg = (tid & 1) * 16;
    int vrow = tid >> 3, vseg = (tid & 7) * 8;
    const float* Pg = probs + ((size_t)bh * SEQ + m0 + prow) * SEQ + pseg;
    const float* Vg = g_qkv + (size_t)(b * SEQ + vrow) * QKVDIM + 2 * HIDDEN + h * HEADD + vseg;

    float acc[2][4][4] = {};

    uint32_t phiB = smem_u32(Phi) + (uint32_t)((wm * 32 + (lane & 15)) * 80 + (lane >> 4) * 16);
    uint32_t ploB = smem_u32(Plo) + (uint32_t)((wm * 32 + (lane & 15)) * 80 + (lane >> 4) * 16);
    uint32_t vhiB = smem_u32(Vhi) + (uint32_t)(wn * 64 + (lane & 15) * 144 + (lane >> 4) * 16);
    uint32_t vloB = smem_u32(Vlo) + (uint32_t)(wn * 64 + (lane & 15) * 144 + (lane >> 4) * 16);

    int NCH = (mt + 1) * 4;
    float4 p0 = *(const float4*)(Pg);     float4 p1 = *(const float4*)(Pg + 4);
    float4 p2 = *(const float4*)(Pg + 8); float4 p3 = *(const float4*)(Pg + 12);
    float4 v0 = *(const float4*)(Vg);     float4 v1 = *(const float4*)(Vg + 4);

    for (int kc = 0; kc < NCH; kc++) {
        {
            float pv[16] = {p0.x,p0.y,p0.z,p0.w, p1.x,p1.y,p1.z,p1.w,
                            p2.x,p2.y,p2.z,p2.w, p3.x,p3.y,p3.z,p3.w};
            uint32_t hw[8], lw[8];
            #pragma unroll
            for (int i = 0; i < 8; i++) {
                hw[i] = pack_hi2(pv[2*i], pv[2*i+1]);
                lw[i] = pack_lo2(pv[2*i], pv[2*i+1]);
            }
            uint32_t off = (uint32_t)(prow * 80 + pseg * 2);
            *(uint4*)((char*)Phi + off)      = make_uint4(hw[0], hw[1], hw[2], hw[3]);
            *(uint4*)((char*)Phi + off + 16) = make_uint4(hw[4], hw[5], hw[6], hw[7]);
            *(uint4*)((char*)Plo + off)      = make_uint4(lw[0], lw[1], lw[2], lw[3]);
            *(uint4*)((char*)Plo + off + 16) = make_uint4(lw[4], lw[5], lw[6], lw[7]);

            float vv[8] = {v0.x,v0.y,v0.z,v0.w, v1.x,v1.y,v1.z,v1.w};
            uint32_t vh[4], vl[4];
            #pragma unroll
            for (int i = 0; i < 4; i++) {
                vh[i] = pack_hi2(vv[2*i], vv[2*i+1]);
                vl[i] = pack_lo2(vv[2*i], vv[2*i+1]);
            }
            uint32_t voff = (uint32_t)(vrow * 144 + vseg * 2);
            *(uint4*)((char*)Vhi + voff) = make_uint4(vh[0], vh[1], vh[2], vh[3]);
            *(uint4*)((char*)Vlo + voff) = make_uint4(vl[0], vl[1], vl[2], vl[3]);
        }
        __syncthreads();
        if (kc + 1 < NCH) {
            const float* Pn = Pg + (size_t)(kc + 1) * 32;
            p0 = *(const float4*)(Pn);     p1 = *(const float4*)(Pn + 4);
            p2 = *(const float4*)(Pn + 8); p3 = *(const float4*)(Pn + 12);
            const float* Vn = Vg + (size_t)(kc + 1) * 32 * QKVDIM;
            v0 = *(const float4*)(Vn);     v1 = *(const float4*)(Vn + 4);
        }
        #pragma unroll
        for (int ks = 0; ks < 2; ks++) {
            uint32_t pk = ks * 32;
            uint32_t vk = ks * 16 * 144;
            uint32_t ahi[2][4], alo[2][4];
            ldmat4(ahi[0][0], ahi[0][1], ahi[0][2], ahi[0][3], phiB + pk);
            ldmat4(ahi[1][0], ahi[1][1], ahi[1][2], ahi[1][3], phiB + 16 * 80 + pk);
            ldmat4(alo[0][0], alo[0][1], alo[0][2], alo[0][3], ploB + pk);
            ldmat4(alo[1][0], alo[1][1], alo[1][2], alo[1][3], ploB + 16 * 80 + pk);
            uint32_t bh_[2][4], bl_[2][4];
            ldmat4t(bh_[0][0], bh_[0][1], bh_[0][2], bh_[0][3], vhiB + vk);
            ldmat4t(bh_[1][0], bh_[1][1], bh_[1][2], bh_[1][3], vhiB + vk + 32);
            ldmat4t(bl_[0][0], bl_[0][1], bl_[0][2], bl_[0][3], vloB + vk);
            ldmat4t(bl_[1][0], bl_[1][1], bl_[1][2], bl_[1][3], vloB + vk + 32);
            #pragma unroll
            for (int mi = 0; mi < 2; mi++)
                #pragma unroll
                for (int hf = 0; hf < 2; hf++)
                    #pragma unroll
                    for (int oc = 0; oc < 2; oc++) {
                        int oct = hf * 2 + oc;
                        mma16816(acc[mi][oct], ahi[mi], bh_[hf][oc*2], bh_[hf][oc*2+1]);
                        mma16816(acc[mi][oct], ahi[mi], bl_[hf][oc*2], bl_[hf][oc*2+1]);
                        mma16816(acc[mi][oct], alo[mi], bh_[hf][oc*2], bh_[hf][oc*2+1]);
                    }
        }
        __syncthreads();
    }

    #pragma unroll
    for (int mi = 0; mi < 2; mi++)
        #pragma unroll
        for (int oct = 0; oct < 4; oct++) {
            int r = m0 + wm * 32 + mi * 16 + (lane >> 2);
            int c = h * HEADD + wn * 32 + oct * 8 + (lane & 3) * 2;
            __nv_bfloat16* row0 = g_attn2 + (size_t)(b * SEQ + r) * KSPLIT;
            __nv_bfloat16* row1 = g_attn2 + (size_t)(b * SEQ + r + 8) * KSPLIT;
            store_split2(row0, c, acc[mi][oct][0], acc[mi][oct][1]);
            store_split2(row1, c, acc[mi][oct][2], acc[mi][oct][3]);
        }
}

// ---------------------------------------------------------------------------
extern "C" void kernel_launch(void* const* d_in, const int* in_sizes, int n_in,
                              void* d_out, int out_size) {
    const float* hs    = (const float*)d_in[0];
    const float* Wqkv  = (const float*)d_in[1];
    const float* Wout  = (const float*)d_in[2];
    const float* gamma = (const float*)d_in[3];
    const float* beta  = (const float*)d_in[4];

    float* out = (float*)d_out;
    const size_t OUT_ELEMS   = (size_t)MROWS * HIDDEN;
    const size_t PROBS_ELEMS = (size_t)BATCH * NHEADS * SEQ * SEQ;

    float* probs;
    if ((size_t)out_size >= OUT_ELEMS + PROBS_ELEMS) {
        probs = out + OUT_ELEMS;
    } else {
        void* p; cudaGetSymbolAddress(&p, g_probs_fb);
        probs = (float*)p;
    }

    void* pq;  cudaGetSymbolAddress(&pq, g_qkv);
    void* pa2; cudaGetSymbolAddress(&pa2, g_a2);
    void* pw1; cudaGetSymbolAddress(&pw1, g_wqkv2);
    void* pw2; cudaGetSymbolAddress(&pw2, g_wout2);
    void* pat; cudaGetSymbolAddress(&pat, g_attn2);
    void* pq2; cudaGetSymbolAddress(&pq2, g_q2);
    void* pk2; cudaGetSymbolAddress(&pk2, g_k2);
    float* qkv = (float*)pq;
    __nv_bfloat16* a2  = (__nv_bfloat16*)pa2;
    __nv_bfloat16* w1  = (__nv_bfloat16*)pw1;
    __nv_bfloat16* w2  = (__nv_bfloat16*)pw2;
    __nv_bfloat16* at2 = (__nv_bfloat16*)pat;
    __nv_bfloat16* q2  = (__nv_bfloat16*)pq2;
    __nv_bfloat16* k2  = (__nv_bfloat16*)pk2;

    static int smem_set = 0;
    if (!smem_set) {
        cudaFuncSetAttribute(gemm_bf16, cudaFuncAttributeMaxDynamicSharedMemorySize, DYNSM);
        cudaFuncSetAttribute(scores_kernel, cudaFuncAttributeMaxDynamicSharedMemorySize, DYNSM);
        smem_set = 1;
    }

    ln_kernel<<<MROWS, 256>>>(hs, gamma, beta);
    conv_w<<<(QKVDIM * HIDDEN / 4 + 255) / 256, 256>>>(Wqkv, w1, QKVDIM * HIDDEN);
    conv_w<<<(HIDDEN * HIDDEN / 4 + 255) / 256, 256>>>(Wout, w2, HIDDEN * HIDDEN);

    gemm_bf16<<<dim3(QKVDIM / 128, MROWS / 128), 256, DYNSM>>>(a2, w1, qkv, QKVDIM);

    rope_kernel<<<dim3(SEQ / 64, BATCH * NHEADS), 128>>>();

    scores_kernel<<<dim3(SEQ / 128, SEQ / 128, BATCH * NHEADS), 256, DYNSM>>>(q2, k2, probs);

    softmax_kernel<<<dim3(SEQ, BATCH * NHEADS), 256>>>(probs);

    pv_kernel<<<dim3(SEQ / 128, BATCH * NHEADS), 256>>>(probs);

    gemm_bf16<<<dim3(HIDDEN / 128, MROWS / 128), 256, DYNSM>>>(at2, w2, out, HIDDEN);
}

// round 10
// speedup vs baseline: 1.3287x; 1.1205x over previous
#include <cuda_runtime.h>
#include <cuda_bf16.h>
#include <cstdint>
#include <math.h>

#define BATCH   2
#define SEQ     2048
#define HIDDEN  1024
#define NHEADS  16
#define HEADD   64
#define MROWS   (BATCH*SEQ)      // 4096
#define QKVDIM  (3*HIDDEN)       // 3072
#define KSPLIT  3072             // K' for dense GEMMs
#define KQK     192              // K' for scores (3*64)
#define ATT_SCALE 0.125f
#define LNEPS   1e-5f

// ---------------- scratch (static device memory) ---------------------------
__device__ __nv_bfloat16 g_a2[(size_t)MROWS * KSPLIT];
__device__ __nv_bfloat16 g_wqkv2[(size_t)QKVDIM * KSPLIT];
__device__ __nv_bfloat16 g_wout2[(size_t)HIDDEN * KSPLIT];
__device__ __nv_bfloat16 g_attn2[(size_t)MROWS * KSPLIT];
__device__ float g_qkv[(size_t)MROWS * QKVDIM];
__device__ __nv_bfloat16 g_q2[(size_t)BATCH * NHEADS * SEQ * KQK];
__device__ __nv_bfloat16 g_k2[(size_t)BATCH * NHEADS * SEQ * KQK];
__device__ float g_lsum[(size_t)BATCH * NHEADS * SEQ];   // row sums of exp
__device__ float g_probs_fb[(size_t)BATCH * NHEADS * SEQ * SEQ];

__device__ __forceinline__ uint32_t smem_u32(const void* p) {
    uint32_t a;
    asm("{ .reg .u64 t; cvta.to.shared.u64 t, %1; cvt.u32.u64 %0, t; }" : "=r"(a) : "l"(p));
    return a;
}

// ---------------- bf16 split helpers ----------------------------------------
__device__ __forceinline__ unsigned short bfb(float v) {
    __nv_bfloat16 h = __float2bfloat16(v);
    return *(unsigned short*)&h;
}
__device__ __forceinline__ float bf2f(unsigned short u) {
    __nv_bfloat16 h = *(__nv_bfloat16*)&u;
    return __bfloat162float(h);
}
__device__ __forceinline__ uint32_t pack_hi2(float a, float b) {
    return (uint32_t)bfb(a) | ((uint32_t)bfb(b) << 16);
}
__device__ __forceinline__ uint32_t pack_lo2(float a, float b) {
    unsigned short ha = bfb(a), hb = bfb(b);
    return (uint32_t)bfb(a - bf2f(ha)) | ((uint32_t)bfb(b - bf2f(hb)) << 16);
}
__device__ __forceinline__ void store_split4(__nv_bfloat16* rowbase, int k,
                                             float v0, float v1, float v2, float v3) {
    uint2 hw = { pack_hi2(v0, v1), pack_hi2(v2, v3) };
    uint2 lw = { pack_lo2(v0, v1), pack_lo2(v2, v3) };
    *(uint2*)(rowbase + k)        = hw;
    *(uint2*)(rowbase + 1024 + k) = hw;
    *(uint2*)(rowbase + 2048 + k) = lw;
}
__device__ __forceinline__ void store_split2(__nv_bfloat16* rowbase, int k, float a, float b) {
    uint32_t hw = pack_hi2(a, b), lw = pack_lo2(a, b);
    *(uint32_t*)(rowbase + k)        = hw;
    *(uint32_t*)(rowbase + 1024 + k) = hw;
    *(uint32_t*)(rowbase + 2048 + k) = lw;
}

// ---------------- LayerNorm -> split bf16 -----------------------------------
__global__ void ln_kernel(const float* __restrict__ hs,
                          const float* __restrict__ gamma,
                          const float* __restrict__ beta) {
    int row = blockIdx.x;
    int t = threadIdx.x;
    const float4* x4 = (const float4*)(hs + (size_t)row * HIDDEN);
    float4 v = x4[t];
    float s  = v.x + v.y + v.z + v.w;
    float sq = v.x*v.x + v.y*v.y + v.z*v.z + v.w*v.w;
    #pragma unroll
    for (int o = 16; o > 0; o >>= 1) {
        s  += __shfl_xor_sync(0xffffffffu, s,  o);
        sq += __shfl_xor_sync(0xffffffffu, sq, o);
    }
    __shared__ float ss[8], ssq[8];
    if ((t & 31) == 0) { ss[t >> 5] = s; ssq[t >> 5] = sq; }
    __syncthreads();
    float tot = 0.f, totq = 0.f;
    #pragma unroll
    for (int i = 0; i < 8; i++) { tot += ss[i]; totq += ssq[i]; }
    float mean = tot * (1.0f / HIDDEN);
    float var  = totq * (1.0f / HIDDEN) - mean * mean;
    float inv  = rsqrtf(var + LNEPS);

    float4 g = ((const float4*)gamma)[t];
    float4 b = ((const float4*)beta)[t];
    float o0 = (v.x - mean) * inv * g.x + b.x;
    float o1 = (v.y - mean) * inv * g.y + b.y;
    float o2 = (v.z - mean) * inv * g.z + b.z;
    float o3 = (v.w - mean) * inv * g.w + b.w;
    store_split4(g_a2 + (size_t)row * KSPLIT, t * 4, o0, o1, o2, o3);
}

// ---------------- weight conversion -----------------------------------------
__global__ void conv_w(const float* __restrict__ W, __nv_bfloat16* __restrict__ W2, int total) {
    int gid = blockIdx.x * blockDim.x + threadIdx.x;
    int i4 = gid * 4;
    if (i4 >= total) return;
    int n = i4 >> 10, k = i4 & 1023;
    float4 w = *(const float4*)(W + i4);
    uint2 hw = { pack_hi2(w.x, w.y), pack_hi2(w.z, w.w) };
    uint2 lw = { pack_lo2(w.x, w.y), pack_lo2(w.z, w.w) };
    __nv_bfloat16* rb = W2 + (size_t)n * KSPLIT;
    *(uint2*)(rb + k)        = hw;
    *(uint2*)(rb + 1024 + k) = lw;
    *(uint2*)(rb + 2048 + k) = hw;
}

// ---------------- zero row sums ----------------------------------------------
__global__ void zero_lsum() {
    int i = blockIdx.x * blockDim.x + threadIdx.x;
    if (i < BATCH * NHEADS * SEQ) g_lsum[i] = 0.f;
}

// ---------------- mma plumbing (R7 config: 4 stages, 3-ahead) ----------------
#define SROWB   80         // bytes per smem row (32 bf16 + 8 pad)
#define KCHUNK  32
#define STAGES  4
#define OPB     (128 * SROWB)      // 10240
#define STAGEB2 (2 * OPB)          // 20480
#define DYNSM   (STAGES * STAGEB2) // 81920

__device__ __forceinline__ void ldmat4(uint32_t& r0, uint32_t& r1,
                                       uint32_t& r2, uint32_t& r3, uint32_t addr) {
    asm volatile("ldmatrix.sync.aligned.m8n8.x4.shared.b16 {%0,%1,%2,%3}, [%4];"
                 : "=r"(r0), "=r"(r1), "=r"(r2), "=r"(r3) : "r"(addr));
}
__device__ __forceinline__ void ldmat4t(uint32_t& r0, uint32_t& r1,
                                        uint32_t& r2, uint32_t& r3, uint32_t addr) {
    asm volatile("ldmatrix.sync.aligned.m8n8.x4.trans.shared.b16 {%0,%1,%2,%3}, [%4];"
                 : "=r"(r0), "=r"(r1), "=r"(r2), "=r"(r3) : "r"(addr));
}
__device__ __forceinline__ void mma16816(float* c, const uint32_t* a, uint32_t b0, uint32_t b1) {
    asm volatile("mma.sync.aligned.m16n8k16.row.col.f32.bf16.bf16.f32 "
                 "{%0,%1,%2,%3}, {%4,%5,%6,%7}, {%8,%9}, {%0,%1,%2,%3};"
                 : "+f"(c[0]), "+f"(c[1]), "+f"(c[2]), "+f"(c[3])
                 : "r"(a[0]), "r"(a[1]), "r"(a[2]), "r"(a[3]), "r"(b0), "r"(b1));
}
__device__ __forceinline__ void cpasync16(uint32_t s, const void* g) {
    asm volatile("cp.async.cg.shared.global [%0], [%1], 16;" :: "r"(s), "l"(g));
}
#define CP_COMMIT() asm volatile("cp.async.commit_group;" ::: "memory")
#define CP_WAIT2()  asm volatile("cp.async.wait_group 2;" ::: "memory")
#define CP_WAIT1()  asm volatile("cp.async.wait_group 1;" ::: "memory")
#define CP_WAIT0()  asm volatile("cp.async.wait_group 0;" ::: "memory")

__device__ __forceinline__ void issue32(uint32_t smb, int slot,
                                        const __nv_bfloat16* pa, const __nv_bfloat16* pb,
                                        uint32_t throff) {
    uint32_t so = smb + (uint32_t)slot * STAGEB2 + throff;
    cpasync16(so,      pa); cpasync16(so + 16, pa + 8);
    uint32_t sb = so + OPB;
    cpasync16(sb,      pb); cpasync16(sb + 16, pb + 8);
    CP_COMMIT();
}

// shared 128x128 mainloop, 256 threads, 8 warps (4m x 2n), warp tile 32x64.
__device__ __forceinline__ void mma_tile_loop(uint32_t smb,
        const __nv_bfloat16* Ath, const __nv_bfloat16* Bth,
        int NCH, int tid, float acc[2][8][4]) {
    int lane = tid & 31, w = tid >> 5;
    int wm = w >> 1, wn = w & 1;
    uint32_t throff = (uint32_t)((tid >> 1) * SROWB + (tid & 1) * 32);
    uint32_t aoff = (uint32_t)((wm * 32 + (lane & 15)) * SROWB + (lane >> 4) * 16);
    uint32_t boff = (uint32_t)((wn * 64 + (lane & 15)) * SROWB + (lane >> 4) * 16);

    issue32(smb, 0, Ath,              Bth,              throff);
    issue32(smb, 1, Ath + KCHUNK,     Bth + KCHUNK,     throff);
    issue32(smb, 2, Ath + 2 * KCHUNK, Bth + 2 * KCHUNK, throff);

    for (int kc = 0; kc < NCH; kc++) {
        if (kc + 2 < NCH)      CP_WAIT2();
        else if (kc + 1 < NCH) CP_WAIT1();
        else                   CP_WAIT0();
        __syncthreads();
        if (kc + 3 < NCH)
            issue32(smb, (kc + 3) & 3, Ath + (size_t)(kc + 3) * KCHUNK,
                    Bth + (size_t)(kc + 3) * KCHUNK, throff);

        uint32_t sb = smb + (uint32_t)(kc & 3) * STAGEB2;
        uint32_t aB = sb + aoff;
        uint32_t bB = sb + OPB + boff;
        #pragma unroll
        for (int ks = 0; ks < 2; ks++) {
            uint32_t koff = ks * 32;
            uint32_t af[2][4];
            ldmat4(af[0][0], af[0][1], af[0][2], af[0][3], aB + koff);
            ldmat4(af[1][0], af[1][1], af[1][2], af[1][3], aB + 16 * SROWB + koff);
            uint32_t bf_[4][4];
            #pragma unroll
            for (int n2 = 0; n2 < 4; n2++)
                ldmat4(bf_[n2][0], bf_[n2][1], bf_[n2][2], bf_[n2][3],
                       bB + n2 * 16 * SROWB + koff);
            #pragma unroll
            for (int mi = 0; mi < 2; mi++)
                #pragma unroll
                for (int ni = 0; ni < 8; ni++) {
                    int n2 = ni >> 1, p = ni & 1;
                    mma16816(acc[mi][ni], af[mi], bf_[n2][p], bf_[n2][p + 2]);
                }
        }
    }
}

// ---------------- dense GEMM -------------------------------------------------
__global__ void __launch_bounds__(256, 2) gemm_bf16(const __nv_bfloat16* __restrict__ A2,
                                                    const __nv_bfloat16* __restrict__ B2,
                                                    float* __restrict__ C, int ldc) {
    extern __shared__ __align__(16) char dynsm[];
    uint32_t smb = smem_u32(dynsm);
    int tid = threadIdx.x, lane = tid & 31, w = tid >> 5;
    int wm = w >> 1, wn = w & 1;
    int m0 = blockIdx.y * 128, n0 = blockIdx.x * 128;
    int row = tid >> 1, half = tid & 1;

    const __nv_bfloat16* Ath = A2 + (size_t)(m0 + row) * KSPLIT + half * 16;
    const __nv_bfloat16* Bth = B2 + (size_t)(n0 + row) * KSPLIT + half * 16;

    float acc[2][8][4] = {};
    mma_tile_loop(smb, Ath, Bth, KSPLIT / KCHUNK, tid, acc);

    #pragma unroll
    for (int mi = 0; mi < 2; mi++)
        #pragma unroll
        for (int ni = 0; ni < 8; ni++) {
            int r = m0 + wm * 32 + mi * 16 + (lane >> 2);
            int c = n0 + wn * 64 + ni * 8 + (lane & 3) * 2;
            float2 w0 = { acc[mi][ni][0], acc[mi][ni][1] };
            float2 w1 = { acc[mi][ni][2], acc[mi][ni][3] };
            *(float2*)(C + (size_t)r * ldc + c)       = w0;
            *(float2*)(C + (size_t)(r + 8) * ldc + c) = w1;
        }
}

// ---------------- RoPE -> split bf16 Q2/K2 ----------------------------------
__global__ void __launch_bounds__(128) rope_kernel() {
    __shared__ uint32_t sm[64][97];
    int bh = blockIdx.y;
    int b = bh >> 4, h = bh & 15;
    int s0 = blockIdx.x * 64;
    int t = threadIdx.x;

    float rq[64], rk[64];
    if (t < 64) {
        int s = s0 + t;
        const float* qp = g_qkv + (size_t)(b * SEQ + s) * QKVDIM + h * HEADD;
        const float* kp = qp + HIDDEN;
        float c[32], sn[32];
        const float LOG_TH = 9.210340371976184f;
        #pragma unroll
        for (int j = 0; j < 32; j++) {
            float freq = __expf(-(float)j * (LOG_TH / 32.0f));
            sincosf((float)s * freq, &sn[j], &c[j]);
        }
        float oq[64], ok[64];
        #pragma unroll
        for (int i = 0; i < 64; i++) { oq[i] = qp[i]; ok[i] = kp[i]; }
        #pragma unroll
        for (int j = 0; j < 32; j++) {
            rq[2*j]   = oq[2*j]   * c[j] - oq[32+j] * sn[j];
            rq[2*j+1] = oq[2*j+1] * c[j] + oq[j]    * sn[j];
            rk[2*j]   = ok[2*j]   * c[j] - ok[32+j] * sn[j];
            rk[2*j+1] = ok[2*j+1] * c[j] + ok[j]    * sn[j];
        }
    }

    if (t < 64) {
        #pragma unroll
        for (int j = 0; j < 32; j++) {
            uint32_t hp = pack_hi2(rq[2*j], rq[2*j+1]);
            sm[t][j]      = hp;
            sm[t][32 + j] = hp;
            sm[t][64 + j] = pack_lo2(rq[2*j], rq[2*j+1]);
        }
    }
    __syncthreads();
    {
        uint32_t* dst = (uint32_t*)(g_q2 + ((size_t)bh * SEQ + s0) * KQK);
        for (int idx = t; idx < 64 * 96; idx += 128) {
            int r = idx / 96, cidx = idx % 96;
            dst[r * 96 + cidx] = sm[r][cidx];
        }
    }
    __syncthreads();

    if (t < 64) {
        #pragma unroll
        for (int j = 0; j < 32; j++) {
            uint32_t hp = pack_hi2(rk[2*j], rk[2*j+1]);
            sm[t][j]      = hp;
            sm[t][32 + j] = pack_lo2(rk[2*j], rk[2*j+1]);
            sm[t][64 + j] = hp;
        }
    }
    __syncthreads();
    {
        uint32_t* dst = (uint32_t*)(g_k2 + ((size_t)bh * SEQ + s0) * KQK);
        for (int idx = t; idx < 64 * 96; idx += 128) {
            int r = idx / 96, cidx = idx % 96;
            dst[r * 96 + cidx] = sm[r][cidx];
        }
    }
}

// ---------------- scores: writes unnormalized exp + row sums -----------------
__global__ void __launch_bounds__(256, 2) scores_kernel(const __nv_bfloat16* __restrict__ Q2,
                                                        const __nv_bfloat16* __restrict__ K2,
                                                        float* __restrict__ probs) {
    int nt = blockIdx.x;
    int mt = 15 - (int)blockIdx.y;
    int bh = blockIdx.z;
    int m0 = mt * 128, n0 = nt * 128;
    int tid = threadIdx.x, lane = tid & 31, w = tid >> 5;
    int wm = w >> 1, wn = w & 1;

    if (nt > mt) {
        int tx = tid & 15, ty = tid >> 4;
        float4 z = {0.f, 0.f, 0.f, 0.f};
        #pragma unroll
        for (int ih = 0; ih < 2; ih++)
            #pragma unroll
            for (int i = 0; i < 4; i++) {
                int rm = m0 + ty * 4 + ih * 64 + i;
                float* rowp = probs + ((size_t)bh * SEQ + rm) * SEQ + n0;
                *(float4*)(rowp + tx * 4)      = z;
                *(float4*)(rowp + tx * 4 + 64) = z;
            }
        return;
    }

    extern __shared__ __align__(16) char dynsm[];
    uint32_t smb = smem_u32(dynsm);
    int row = tid >> 1, half = tid & 1;
    const __nv_bfloat16* Ath = Q2 + ((size_t)bh * SEQ + m0 + row) * KQK + half * 16;
    const __nv_bfloat16* Bth = K2 + ((size_t)bh * SEQ + n0 + row) * KQK + half * 16;

    float acc[2][8][4] = {};
    mma_tile_loop(smb, Ath, Bth, KQK / KCHUNK, tid, acc);

    float* pb = probs + (size_t)bh * SEQ * SEQ;
    float* ls = g_lsum + (size_t)bh * SEQ;

    #pragma unroll
    for (int mi = 0; mi < 2; mi++) {
        int r = m0 + wm * 32 + mi * 16 + (lane >> 2);
        float sr = 0.f, sr8 = 0.f;
        #pragma unroll
        for (int ni = 0; ni < 8; ni++) {
            int c = n0 + wn * 64 + ni * 8 + (lane & 3) * 2;
            float e0, e1, e2, e3;
            if (nt < mt) {
                e0 = __expf(acc[mi][ni][0] * ATT_SCALE);
                e1 = __expf(acc[mi][ni][1] * ATT_SCALE);
                e2 = __expf(acc[mi][ni][2] * ATT_SCALE);
                e3 = __expf(acc[mi][ni][3] * ATT_SCALE);
            } else {
                e0 = (c     <= r)     ? __expf(acc[mi][ni][0] * ATT_SCALE) : 0.f;
                e1 = (c + 1 <= r)     ? __expf(acc[mi][ni][1] * ATT_SCALE) : 0.f;
                e2 = (c     <= r + 8) ? __expf(acc[mi][ni][2] * ATT_SCALE) : 0.f;
                e3 = (c + 1 <= r + 8) ? __expf(acc[mi][ni][3] * ATT_SCALE) : 0.f;
            }
            float2 w0 = { e0, e1 };
            float2 w1 = { e2, e3 };
            *(float2*)(pb + (size_t)r * SEQ + c)       = w0;
            *(float2*)(pb + (size_t)(r + 8) * SEQ + c) = w1;
            sr  += e0 + e1;
            sr8 += e2 + e3;
        }
        sr  += __shfl_xor_sync(0xffffffffu, sr, 1);
        sr  += __shfl_xor_sync(0xffffffffu, sr, 2);
        sr8 += __shfl_xor_sync(0xffffffffu, sr8, 1);
        sr8 += __shfl_xor_sync(0xffffffffu, sr8, 2);
        if ((lane & 3) == 0) {
            atomicAdd(ls + r, sr);
            atomicAdd(ls + r + 8, sr8);
        }
    }
}

// ---------------- PV via mma: normalize + write probs + accumulate ----------
__global__ void __launch_bounds__(256) pv_kernel(float* __restrict__ probs) {
    __shared__ __align__(16) __nv_bfloat16 Phi[128 * 40];
    __shared__ __align__(16) __nv_bfloat16 Plo[128 * 40];
    __shared__ __align__(16) __nv_bfloat16 Vhi[32 * 72];
    __shared__ __align__(16) __nv_bfloat16 Vlo[32 * 72];

    int bh = blockIdx.y;
    int mt = (int)gridDim.x - 1 - (int)blockIdx.x;
    int b = bh >> 4, h = bh & 15;
    int m0 = mt * 128;
    int tid = threadIdx.x, lane = tid & 31, w = tid >> 5;
    int wm = w >> 1, wn = w & 1;

    int prow = tid >> 1, pseg = (tid & 1) * 16;
    int vrow = tid >> 3, vseg = (tid & 7) * 8;
    float* Pg = probs + ((size_t)bh * SEQ + m0 + prow) * SEQ + pseg;
    const float* Vg = g_qkv + (size_t)(b * SEQ + vrow) * QKVDIM + 2 * HIDDEN + h * HEADD + vseg;

    float invl = 1.0f / g_lsum[(size_t)bh * SEQ + m0 + prow];

    float acc[2][4][4] = {};

    uint32_t phiB = smem_u32(Phi) + (uint32_t)((wm * 32 + (lane & 15)) * 80 + (lane >> 4) * 16);
    uint32_t ploB = smem_u32(Plo) + (uint32_t)((wm * 32 + (lane & 15)) * 80 + (lane >> 4) * 16);
    uint32_t vhiB = smem_u32(Vhi) + (uint32_t)(wn * 64 + (lane & 15) * 144 + (lane >> 4) * 16);
    uint32_t vloB = smem_u32(Vlo) + (uint32_t)(wn * 64 + (lane & 15) * 144 + (lane >> 4) * 16);

    int NCH = (mt + 1) * 4;
    float4 p0 = *(const float4*)(Pg);     float4 p1 = *(const float4*)(Pg + 4);
    float4 p2 = *(const float4*)(Pg + 8); float4 p3 = *(const float4*)(Pg + 12);
    float4 v0 = *(const float4*)(Vg);     float4 v1 = *(const float4*)(Vg + 4);

    for (int kc = 0; kc < NCH; kc++) {
        {
            float pv[16] = {p0.x,p0.y,p0.z,p0.w, p1.x,p1.y,p1.z,p1.w,
                            p2.x,p2.y,p2.z,p2.w, p3.x,p3.y,p3.z,p3.w};
            #pragma unroll
            for (int i = 0; i < 16; i++) pv[i] *= invl;
            // write normalized probs back (same addresses just read)
            float* Pw = Pg + (size_t)kc * 32;
            *(float4*)(Pw)      = make_float4(pv[0],  pv[1],  pv[2],  pv[3]);
            *(float4*)(Pw + 4)  = make_float4(pv[4],  pv[5],  pv[6],  pv[7]);
            *(float4*)(Pw + 8)  = make_float4(pv[8],  pv[9],  pv[10], pv[11]);
            *(float4*)(Pw + 12) = make_float4(pv[12], pv[13], pv[14], pv[15]);

            uint32_t hw[8], lw[8];
            #pragma unroll
            for (int i = 0; i < 8; i++) {
                hw[i] = pack_hi2(pv[2*i], pv[2*i+1]);
                lw[i] = pack_lo2(pv[2*i], pv[2*i+1]);
            }
            uint32_t off = (uint32_t)(prow * 80 + pseg * 2);
            *(uint4*)((char*)Phi + off)      = make_uint4(hw[0], hw[1], hw[2], hw[3]);
            *(uint4*)((char*)Phi + off + 16) = make_uint4(hw[4], hw[5], hw[6], hw[7]);
            *(uint4*)((char*)Plo + off)      = make_uint4(lw[0], lw[1], lw[2], lw[3]);
            *(uint4*)((char*)Plo + off + 16) = make_uint4(lw[4], lw[5], lw[6], lw[7]);

            float vv[8] = {v0.x,v0.y,v0.z,v0.w, v1.x,v1.y,v1.z,v1.w};
            uint32_t vh[4], vl[4];
            #pragma unroll
            for (int i = 0; i < 4; i++) {
                vh[i] = pack_hi2(vv[2*i], vv[2*i+1]);
                vl[i] = pack_lo2(vv[2*i], vv[2*i+1]);
            }
            uint32_t voff = (uint32_t)(vrow * 144 + vseg * 2);
            *(uint4*)((char*)Vhi + voff) = make_uint4(vh[0], vh[1], vh[2], vh[3]);
            *(uint4*)((char*)Vlo + voff) = make_uint4(vl[0], vl[1], vl[2], vl[3]);
        }
        __syncthreads();
        if (kc + 1 < NCH) {
            const float* Pn = Pg + (size_t)(kc + 1) * 32;
            p0 = *(const float4*)(Pn);     p1 = *(const float4*)(Pn + 4);
            p2 = *(const float4*)(Pn + 8); p3 = *(const float4*)(Pn + 12);
            const float* Vn = Vg + (size_t)(kc + 1) * 32 * QKVDIM;
            v0 = *(const float4*)(Vn);     v1 = *(const float4*)(Vn + 4);
        }
        #pragma unroll
        for (int ks = 0; ks < 2; ks++) {
            uint32_t pk = ks * 32;
            uint32_t vk = ks * 16 * 144;
            uint32_t ahi[2][4], alo[2][4];
            ldmat4(ahi[0][0], ahi[0][1], ahi[0][2], ahi[0][3], phiB + pk);
            ldmat4(ahi[1][0], ahi[1][1], ahi[1][2], ahi[1][3], phiB + 16 * 80 + pk);
            ldmat4(alo[0][0], alo[0][1], alo[0][2], alo[0][3], ploB + pk);
            ldmat4(alo[1][0], alo[1][1], alo[1][2], alo[1][3], ploB + 16 * 80 + pk);
            uint32_t bh_[2][4], bl_[2][4];
            ldmat4t(bh_[0][0], bh_[0][1], bh_[0][2], bh_[0][3], vhiB + vk);
            ldmat4t(bh_[1][0], bh_[1][1], bh_[1][2], bh_[1][3], vhiB + vk + 32);
            ldmat4t(bl_[0][0], bl_[0][1], bl_[0][2], bl_[0][3], vloB + vk);
            ldmat4t(bl_[1][0], bl_[1][1], bl_[1][2], bl_[1][3], vloB + vk + 32);
            #pragma unroll
            for (int mi = 0; mi < 2; mi++)
                #pragma unroll
                for (int hf = 0; hf < 2; hf++)
                    #pragma unroll
                    for (int oc = 0; oc < 2; oc++) {
                        int oct = hf * 2 + oc;
                        mma16816(acc[mi][oct], ahi[mi], bh_[hf][oc*2], bh_[hf][oc*2+1]);
                        mma16816(acc[mi][oct], ahi[mi], bl_[hf][oc*2], bl_[hf][oc*2+1]);
                        mma16816(acc[mi][oct], alo[mi], bh_[hf][oc*2], bh_[hf][oc*2+1]);
                    }
        }
        __syncthreads();
    }

    #pragma unroll
    for (int mi = 0; mi < 2; mi++)
        #pragma unroll
        for (int oct = 0; oct < 4; oct++) {
            int r = m0 + wm * 32 + mi * 16 + (lane >> 2);
            int c = h * HEADD + wn * 32 + oct * 8 + (lane & 3) * 2;
            __nv_bfloat16* row0 = g_attn2 + (size_t)(b * SEQ + r) * KSPLIT;
            __nv_bfloat16* row1 = g_attn2 + (size_t)(b * SEQ + r + 8) * KSPLIT;
            store_split2(row0, c, acc[mi][oct][0], acc[mi][oct][1]);
            store_split2(row1, c, acc[mi][oct][2], acc[mi][oct][3]);
        }
}

// ---------------------------------------------------------------------------
extern "C" void kernel_launch(void* const* d_in, const int* in_sizes, int n_in,
                              void* d_out, int out_size) {
    const float* hs    = (const float*)d_in[0];
    const float* Wqkv  = (const float*)d_in[1];
    const float* Wout  = (const float*)d_in[2];
    const float* gamma = (const float*)d_in[3];
    const float* beta  = (const float*)d_in[4];

    float* out = (float*)d_out;
    const size_t OUT_ELEMS   = (size_t)MROWS * HIDDEN;
    const size_t PROBS_ELEMS = (size_t)BATCH * NHEADS * SEQ * SEQ;

    float* probs;
    if ((size_t)out_size >= OUT_ELEMS + PROBS_ELEMS) {
        probs = out + OUT_ELEMS;
    } else {
        void* p; cudaGetSymbolAddress(&p, g_probs_fb);
        probs = (float*)p;
    }

    void* pq;  cudaGetSymbolAddress(&pq, g_qkv);
    void* pa2; cudaGetSymbolAddress(&pa2, g_a2);
    void* pw1; cudaGetSymbolAddress(&pw1, g_wqkv2);
    void* pw2; cudaGetSymbolAddress(&pw2, g_wout2);
    void* pat; cudaGetSymbolAddress(&pat, g_attn2);
    void* pq2; cudaGetSymbolAddress(&pq2, g_q2);
    void* pk2; cudaGetSymbolAddress(&pk2, g_k2);
    float* qkv = (float*)pq;
    __nv_bfloat16* a2  = (__nv_bfloat16*)pa2;
    __nv_bfloat16* w1  = (__nv_bfloat16*)pw1;
    __nv_bfloat16* w2  = (__nv_bfloat16*)pw2;
    __nv_bfloat16* at2 = (__nv_bfloat16*)pat;
    __nv_bfloat16* q2  = (__nv_bfloat16*)pq2;
    __nv_bfloat16* k2  = (__nv_bfloat16*)pk2;

    static int smem_set = 0;
    if (!smem_set) {
        cudaFuncSetAttribute(gemm_bf16, cudaFuncAttributeMaxDynamicSharedMemorySize, DYNSM);
        cudaFuncSetAttribute(scores_kernel, cudaFuncAttributeMaxDynamicSharedMemorySize, DYNSM);
        smem_set = 1;
    }

    ln_kernel<<<MROWS, 256>>>(hs, gamma, beta);
    conv_w<<<(QKVDIM * HIDDEN / 4 + 255) / 256, 256>>>(Wqkv, w1, QKVDIM * HIDDEN);
    conv_w<<<(HIDDEN * HIDDEN / 4 + 255) / 256, 256>>>(Wout, w2, HIDDEN * HIDDEN);
    zero_lsum<<<(BATCH * NHEADS * SEQ + 255) / 256, 256>>>();

    gemm_bf16<<<dim3(QKVDIM / 128, MROWS / 128), 256, DYNSM>>>(a2, w1, qkv, QKVDIM);

    rope_kernel<<<dim3(SEQ / 64, BATCH * NHEADS), 128>>>();

    scores_kernel<<<dim3(SEQ / 128, SEQ / 128, BATCH * NHEADS), 256, DYNSM>>>(q2, k2, probs);

    pv_kernel<<<dim3(SEQ / 128, BATCH * NHEADS), 256>>>(probs);

    gemm_bf16<<<dim3(HIDDEN / 128, MROWS / 128), 256, DYNSM>>>(at2, w2, out, HIDDEN);
}